// round 2
// baseline (speedup 1.0000x reference)
#include <cuda_runtime.h>
#include <cuda_bf16.h>
#include <math.h>

// Problem constants
#define P_NUM 64
#define B_NUM 32
#define D_DIM 512
#define H_DIM 2048
#define E_NUM 16
#define N_TOK (P_NUM * B_NUM)        // 2048 tokens
#define N_ROWS (N_TOK * 2)           // 4096 assignment rows (2 slots per token)

// ---- device scratch (no allocations allowed) ----
__device__ int   g_cnt[E_NUM];
__device__ int   g_tok [E_NUM][N_TOK];   // token id per bucket entry
__device__ int   g_row [E_NUM][N_TOK];   // 2*t + slot
__device__ float g_gate[E_NUM][N_TOK];   // softmax gate weight
__device__ float g_H[(size_t)N_ROWS * H_DIM]; // 32 MB hidden scratch
__device__ float g_Y[(size_t)N_ROWS * D_DIM]; // 8 MB per-slot output

// ---------------------------------------------------------------------------
__global__ void reset_kernel() {
    if (threadIdx.x < E_NUM) g_cnt[threadIdx.x] = 0;
}

// ---------------------------------------------------------------------------
// One warp per token: values = x . w_gate  -> top-2 -> softmax -> bucket.
__global__ void gating_kernel(const float* __restrict__ x,
                              const float* __restrict__ wg) {
    int t = blockIdx.x;
    __shared__ float xs[D_DIM];
    __shared__ float vals[E_NUM];
    int tid = threadIdx.x; // blockDim = 32

    const float4* xr = reinterpret_cast<const float4*>(x + (size_t)t * D_DIM);
    float4* xs4 = reinterpret_cast<float4*>(xs);
    #pragma unroll
    for (int i = tid; i < D_DIM / 4; i += 32) xs4[i] = xr[i];
    __syncwarp();

    if (tid < E_NUM) {
        float acc = 0.f;
        #pragma unroll 8
        for (int d = 0; d < D_DIM; d++) acc += xs[d] * wg[d * E_NUM + tid];
        vals[tid] = acc;
    }
    __syncwarp();

    if (tid == 0) {
        float v1 = -INFINITY, v2 = -INFINITY;
        int i1 = 0, i2 = 0;
        #pragma unroll
        for (int e = 0; e < E_NUM; e++) {
            float v = vals[e];
            if (v > v1) { v2 = v1; i2 = i1; v1 = v; i1 = e; }
            else if (v > v2) { v2 = v; i2 = e; }
        }
        // softmax over {v1, v2} (v1 >= v2)
        float ex = __expf(v2 - v1);
        float inv = 1.f / (1.f + ex);
        float gA = inv;          // weight for top-1
        float gB = ex * inv;     // weight for top-2

        int p1 = atomicAdd(&g_cnt[i1], 1);
        g_tok[i1][p1] = t; g_row[i1][p1] = 2 * t;     g_gate[i1][p1] = gA;
        int p2 = atomicAdd(&g_cnt[i2], 1);
        g_tok[i2][p2] = t; g_row[i2][p2] = 2 * t + 1; g_gate[i2][p2] = gB;
    }
}

// ---------------------------------------------------------------------------
// Tiled fp32 grouped GEMM, stage 1: H = relu(Xg @ W1[e] + b1[e])
// Tiles: BM=128, BN=64, BK=16; 256 threads; 8x4 micro-tile.
#define BM 128
#define BN 64
#define BK 16

__global__ __launch_bounds__(256)
void gemm1_kernel(const float* __restrict__ x,
                  const float* __restrict__ w1,
                  const float* __restrict__ b1) {
    const int e   = blockIdx.z;
    const int cnt = g_cnt[e];
    const int m0  = blockIdx.y * BM;
    if (m0 >= cnt) return;
    const int n0  = blockIdx.x * BN;

    __shared__ float As[BK][BM];
    __shared__ float Bs[BK][BN];

    const int tid = threadIdx.x;
    const int tx  = tid & 15;
    const int ty  = tid >> 4;

    const float* Bbase = w1 + (size_t)e * D_DIM * H_DIM;

    // A load mapping: each thread loads 8 floats (2 float4) of one gathered row
    const int ar  = tid >> 1;
    const int ac4 = (tid & 1) * 8;
    const int gm  = m0 + ar;
    const float* arow = (gm < cnt) ? (x + (size_t)g_tok[e][gm] * D_DIM) : nullptr;

    // B load mapping: one float4 per thread
    const int bk = tid >> 4;
    const int bn = (tid & 15) * 4;

    float acc[8][4];
    #pragma unroll
    for (int i = 0; i < 8; i++)
        #pragma unroll
        for (int j = 0; j < 4; j++) acc[i][j] = 0.f;

    for (int k0 = 0; k0 < D_DIM; k0 += BK) {
        float4 a0 = make_float4(0.f, 0.f, 0.f, 0.f), a1 = a0;
        if (arow) {
            a0 = *reinterpret_cast<const float4*>(arow + k0 + ac4);
            a1 = *reinterpret_cast<const float4*>(arow + k0 + ac4 + 4);
        }
        As[ac4 + 0][ar] = a0.x; As[ac4 + 1][ar] = a0.y;
        As[ac4 + 2][ar] = a0.z; As[ac4 + 3][ar] = a0.w;
        As[ac4 + 4][ar] = a1.x; As[ac4 + 5][ar] = a1.y;
        As[ac4 + 6][ar] = a1.z; As[ac4 + 7][ar] = a1.w;

        float4 bv = *reinterpret_cast<const float4*>(
            Bbase + (size_t)(k0 + bk) * H_DIM + n0 + bn);
        *reinterpret_cast<float4*>(&Bs[bk][bn]) = bv;
        __syncthreads();

        #pragma unroll
        for (int kk = 0; kk < BK; kk++) {
            float4 af0 = *reinterpret_cast<float4*>(&As[kk][ty * 8]);
            float4 af1 = *reinterpret_cast<float4*>(&As[kk][ty * 8 + 4]);
            float4 bf  = *reinterpret_cast<float4*>(&Bs[kk][tx * 4]);
            float a[8] = {af0.x, af0.y, af0.z, af0.w, af1.x, af1.y, af1.z, af1.w};
            float b[4] = {bf.x, bf.y, bf.z, bf.w};
            #pragma unroll
            for (int i = 0; i < 8; i++)
                #pragma unroll
                for (int j = 0; j < 4; j++) acc[i][j] += a[i] * b[j];
        }
        __syncthreads();
    }

    float4 bias = *reinterpret_cast<const float4*>(
        b1 + (size_t)e * H_DIM + n0 + tx * 4);
    #pragma unroll
    for (int i = 0; i < 8; i++) {
        int m = m0 + ty * 8 + i;
        if (m >= cnt) continue;
        int row = g_row[e][m];
        float4 v;
        v.x = fmaxf(acc[i][0] + bias.x, 0.f);
        v.y = fmaxf(acc[i][1] + bias.y, 0.f);
        v.z = fmaxf(acc[i][2] + bias.z, 0.f);
        v.w = fmaxf(acc[i][3] + bias.w, 0.f);
        *reinterpret_cast<float4*>(g_H + (size_t)row * H_DIM + n0 + tx * 4) = v;
    }
}

// ---------------------------------------------------------------------------
// Stage 2: Y = gate * (Hg @ W2[e] + b2[e])
__global__ __launch_bounds__(256)
void gemm2_kernel(const float* __restrict__ w2,
                  const float* __restrict__ b2) {
    const int e   = blockIdx.z;
    const int cnt = g_cnt[e];
    const int m0  = blockIdx.y * BM;
    if (m0 >= cnt) return;
    const int n0  = blockIdx.x * BN;

    __shared__ float As[BK][BM];
    __shared__ float Bs[BK][BN];

    const int tid = threadIdx.x;
    const int tx  = tid & 15;
    const int ty  = tid >> 4;

    const float* Bbase = w2 + (size_t)e * H_DIM * D_DIM;

    const int ar  = tid >> 1;
    const int ac4 = (tid & 1) * 8;
    const int gm  = m0 + ar;
    const float* arow = (gm < cnt) ? (g_H + (size_t)g_row[e][gm] * H_DIM) : nullptr;

    const int bk = tid >> 4;
    const int bn = (tid & 15) * 4;

    float acc[8][4];
    #pragma unroll
    for (int i = 0; i < 8; i++)
        #pragma unroll
        for (int j = 0; j < 4; j++) acc[i][j] = 0.f;

    for (int k0 = 0; k0 < H_DIM; k0 += BK) {
        float4 a0 = make_float4(0.f, 0.f, 0.f, 0.f), a1 = a0;
        if (arow) {
            a0 = *reinterpret_cast<const float4*>(arow + k0 + ac4);
            a1 = *reinterpret_cast<const float4*>(arow + k0 + ac4 + 4);
        }
        As[ac4 + 0][ar] = a0.x; As[ac4 + 1][ar] = a0.y;
        As[ac4 + 2][ar] = a0.z; As[ac4 + 3][ar] = a0.w;
        As[ac4 + 4][ar] = a1.x; As[ac4 + 5][ar] = a1.y;
        As[ac4 + 6][ar] = a1.z; As[ac4 + 7][ar] = a1.w;

        float4 bv = *reinterpret_cast<const float4*>(
            Bbase + (size_t)(k0 + bk) * D_DIM + n0 + bn);
        *reinterpret_cast<float4*>(&Bs[bk][bn]) = bv;
        __syncthreads();

        #pragma unroll
        for (int kk = 0; kk < BK; kk++) {
            float4 af0 = *reinterpret_cast<float4*>(&As[kk][ty * 8]);
            float4 af1 = *reinterpret_cast<float4*>(&As[kk][ty * 8 + 4]);
            float4 bf  = *reinterpret_cast<float4*>(&Bs[kk][tx * 4]);
            float a[8] = {af0.x, af0.y, af0.z, af0.w, af1.x, af1.y, af1.z, af1.w};
            float b[4] = {bf.x, bf.y, bf.z, bf.w};
            #pragma unroll
            for (int i = 0; i < 8; i++)
                #pragma unroll
                for (int j = 0; j < 4; j++) acc[i][j] += a[i] * b[j];
        }
        __syncthreads();
    }

    float4 bias = *reinterpret_cast<const float4*>(
        b2 + (size_t)e * D_DIM + n0 + tx * 4);
    #pragma unroll
    for (int i = 0; i < 8; i++) {
        int m = m0 + ty * 8 + i;
        if (m >= cnt) continue;
        int   row = g_row[e][m];
        float g   = g_gate[e][m];
        float4 v;
        v.x = g * (acc[i][0] + bias.x);
        v.y = g * (acc[i][1] + bias.y);
        v.z = g * (acc[i][2] + bias.z);
        v.w = g * (acc[i][3] + bias.w);
        *reinterpret_cast<float4*>(g_Y + (size_t)row * D_DIM + n0 + tx * 4) = v;
    }
}

// ---------------------------------------------------------------------------
// out[t][d] = Y[2t][d] + Y[2t+1][d]   (deterministic, no atomics)
__global__ void combine_kernel(float* __restrict__ out) {
    int i = blockIdx.x * blockDim.x + threadIdx.x; // float4 index
    if (i >= N_TOK * D_DIM / 4) return;
    int t  = i / (D_DIM / 4);
    int d4 = i % (D_DIM / 4);
    const float4* y0 = reinterpret_cast<const float4*>(g_Y + (size_t)(2 * t)     * D_DIM) + d4;
    const float4* y1 = reinterpret_cast<const float4*>(g_Y + (size_t)(2 * t + 1) * D_DIM) + d4;
    float4 a = *y0, b = *y1;
    float4 r = make_float4(a.x + b.x, a.y + b.y, a.z + b.z, a.w + b.w);
    reinterpret_cast<float4*>(out)[i] = r;
}

// ---------------------------------------------------------------------------
// aux = 0.01 * var(importance, ddof=1) / (mean(importance)^2 + 1e-10)
__global__ void aux_kernel(float* __restrict__ out, int out_size) {
    __shared__ float imp[E_NUM];
    int w = threadIdx.x >> 5, lane = threadIdx.x & 31; // 512 threads = 16 warps
    int cnt = g_cnt[w];
    float s = 0.f;
    for (int i = lane; i < cnt; i += 32) s += g_gate[w][i];
    #pragma unroll
    for (int off = 16; off > 0; off >>= 1) s += __shfl_down_sync(0xffffffffu, s, off);
    if (lane == 0) imp[w] = s;
    __syncthreads();
    if (threadIdx.x == 0) {
        float mean = 0.f;
        #pragma unroll
        for (int e = 0; e < E_NUM; e++) mean += imp[e];
        mean *= (1.f / E_NUM);
        float var = 0.f;
        #pragma unroll
        for (int e = 0; e < E_NUM; e++) {
            float d = imp[e] - mean; var += d * d;
        }
        var *= (1.f / (E_NUM - 1));
        float aux = 0.01f * var / (mean * mean + 1e-10f);
        if (out_size > N_TOK * D_DIM) out[out_size - 1] = aux;
    }
}

// ---------------------------------------------------------------------------
extern "C" void kernel_launch(void* const* d_in, const int* in_sizes, int n_in,
                              void* d_out, int out_size) {
    const float* x  = (const float*)d_in[0];
    const float* wg = (const float*)d_in[1];
    const float* w1 = (const float*)d_in[2];
    const float* b1 = (const float*)d_in[3];
    const float* w2 = (const float*)d_in[4];
    const float* b2 = (const float*)d_in[5];
    float* out = (float*)d_out;

    reset_kernel<<<1, 32>>>();
    gating_kernel<<<N_TOK, 32>>>(x, wg);
    // GEMM1: N=2048 -> 32 n-tiles; worst-case 16 m-tiles (cnt up to 2048); 16 experts
    gemm1_kernel<<<dim3(H_DIM / BN, N_TOK / BM, E_NUM), 256>>>(x, w1, b1);
    // GEMM2: N=512 -> 8 n-tiles
    gemm2_kernel<<<dim3(D_DIM / BN, N_TOK / BM, E_NUM), 256>>>(w2, b2);
    combine_kernel<<<(N_TOK * D_DIM / 4 + 255) / 256, 256>>>(out);
    aux_kernel<<<1, 512>>>(out, out_size);
}

// round 10
// speedup vs baseline: 1.3428x; 1.3428x over previous
#include <cuda_runtime.h>
#include <cuda_fp16.h>
#include <cstdint>
#include <math.h>

// Problem constants
#define P_NUM 64
#define B_NUM 32
#define D_DIM 512
#define H_DIM 2048
#define E_NUM 16
#define N_TOK (P_NUM * B_NUM)        // 2048 tokens
#define N_ROWS (N_TOK * 2)           // 4096 assignment rows

// ---- device scratch. NEVER passed as kernel args from host (host shadow
// trap: on GB300/ATS the GPU silently writes the HOST shadow copy). All
// kernels reference these symbols directly in device code. ----
__device__ int   g_cnt[E_NUM];
__device__ int   g_tok [E_NUM][N_TOK];
__device__ int   g_row [E_NUM][N_TOK];
__device__ float g_gate[E_NUM][N_TOK];
__device__ float g_H [(size_t)N_ROWS * H_DIM]; // 32 MB hidden scratch
__device__ float g_Y [(size_t)N_ROWS * D_DIM]; // split-0 output
__device__ float g_Y2[(size_t)N_ROWS * D_DIM]; // split-1 output

// ===========================================================================
// helpers
// ===========================================================================
__device__ __forceinline__ void mma_f16(float* c,
                                        uint32_t a0, uint32_t a1, uint32_t a2, uint32_t a3,
                                        uint32_t b0, uint32_t b1) {
    asm volatile(
        "mma.sync.aligned.m16n8k16.row.col.f32.f16.f16.f32 "
        "{%0,%1,%2,%3}, {%4,%5,%6,%7}, {%8,%9}, {%0,%1,%2,%3};"
        : "+f"(c[0]), "+f"(c[1]), "+f"(c[2]), "+f"(c[3])
        : "r"(a0), "r"(a1), "r"(a2), "r"(a3), "r"(b0), "r"(b1));
}

__device__ __forceinline__ uint32_t pack2h(__half e0, __half e1) {
    return (uint32_t)__half_as_ushort(e0) |
           ((uint32_t)__half_as_ushort(e1) << 16);
}

// split float2 -> packed f16 hi pair + lo pair (element0 in low 16 bits)
__device__ __forceinline__ void split2(float2 v, uint32_t& hi, uint32_t& lo) {
    __half hx = __float2half_rn(v.x);
    __half hy = __float2half_rn(v.y);
    __half lx = __float2half_rn(v.x - __half2float(hx));
    __half ly = __float2half_rn(v.y - __half2float(hy));
    hi = pack2h(hx, hy);
    lo = pack2h(lx, ly);
}

// ===========================================================================
// small kernels (identical to R1 pass)
// ===========================================================================
__global__ void reset_kernel() {
    if (threadIdx.x < E_NUM) g_cnt[threadIdx.x] = 0;
}

__global__ void gating_kernel(const float* __restrict__ x,
                              const float* __restrict__ wg) {
    int t = blockIdx.x;
    __shared__ float xs[D_DIM];
    __shared__ float vals[E_NUM];
    int tid = threadIdx.x; // 32

    const float4* xr = reinterpret_cast<const float4*>(x + (size_t)t * D_DIM);
    float4* xs4 = reinterpret_cast<float4*>(xs);
    #pragma unroll
    for (int i = tid; i < D_DIM / 4; i += 32) xs4[i] = xr[i];
    __syncwarp();

    if (tid < E_NUM) {
        float acc = 0.f;
        #pragma unroll 8
        for (int d = 0; d < D_DIM; d++) acc += xs[d] * wg[d * E_NUM + tid];
        vals[tid] = acc;
    }
    __syncwarp();

    if (tid == 0) {
        float v1 = -INFINITY, v2 = -INFINITY;
        int i1 = 0, i2 = 0;
        #pragma unroll
        for (int e = 0; e < E_NUM; e++) {
            float v = vals[e];
            if (v > v1) { v2 = v1; i2 = i1; v1 = v; i1 = e; }
            else if (v > v2) { v2 = v; i2 = e; }
        }
        float ex = __expf(v2 - v1);
        float inv = 1.f / (1.f + ex);
        int p1 = atomicAdd(&g_cnt[i1], 1);
        g_tok[i1][p1] = t; g_row[i1][p1] = 2 * t;     g_gate[i1][p1] = inv;
        int p2 = atomicAdd(&g_cnt[i2], 1);
        g_tok[i2][p2] = t; g_row[i2][p2] = 2 * t + 1; g_gate[i2][p2] = ex * inv;
    }
}

// ===========================================================================
// Grouped GEMM via mma.sync f16 (3x split). CTA tile 128x128, K-slab 32.
//   D[m][n] = sum_k A[m][k] * W[k][n]
// RELU=true : A = Asrc (x) gathered by g_tok; D = g_H rows g_row; relu(.+bias)
// RELU=false: A = g_H gathered by g_row; D = g_Y/g_Y2 by split; gate*(.+bias@split0)
// ===========================================================================
#define BT_SWZ(n, k) ((k) ^ ((((n) >> 3) & 7) << 2))

template<int KDIM, int LDA, int NTOT, bool RELU, int NSPLIT>
__global__ __launch_bounds__(256)
void moe_mma(const float* __restrict__ Asrc,
             const float* __restrict__ Wsrc,
             const float* __restrict__ bias) {
    const int e     = blockIdx.z / NSPLIT;
    const int split = blockIdx.z % NSPLIT;
    const int cnt = g_cnt[e];
    const int m0  = blockIdx.y * 128;
    if (m0 >= cnt) return;
    const int n0  = blockIdx.x * 128;

    const int KSEG = KDIM / NSPLIT;
    const int kb   = split * KSEG;

    __shared__ float As[128][36];
    __shared__ float Bt[128][36];
    __shared__ float bias_s[128];

    const int tid = threadIdx.x;
    const int wid = tid >> 5, lid = tid & 31;
    const int wm = wid & 1;
    const int wn = wid >> 1;
    const int qid = lid >> 2;
    const int tig = lid & 3;

    // device-symbol plumbing (NEVER from host)
    const float* Abase = RELU ? Asrc : g_H;
    float* Dst = RELU ? g_H : (split == 0 ? g_Y : g_Y2);

    const float* W = Wsrc + (size_t)e * KDIM * NTOT;

    if (tid < 128) bias_s[tid] = bias[(size_t)e * NTOT + n0 + tid];

    // A staging: thread -> row r = tid>>1, k-half kh = tid&1 (16 of 32 floats)
    const int r  = tid >> 1;
    const int kh = tid & 1;
    const int m  = m0 + r;
    const bool mvalid = (m < cnt);
    const int asrc_row = mvalid ? (RELU ? g_tok[e][m] : g_row[e][m]) : 0;
    const float* arow = Abase + (size_t)asrc_row * LDA + kb + kh * 16;
    // B staging: thread -> k-pair 2*bk2, cols c0..c0+7
    const int bk2 = tid >> 4;
    const int c0  = (tid & 15) * 8;
    const float* brow = W + (size_t)(kb + 2 * bk2) * NTOT + n0 + c0;

    const int NS = KSEG / 32;
    float4 aV[4];
    float4 bV[4];

    float acc[4][4][4];
    #pragma unroll
    for (int i = 0; i < 4; i++)
        #pragma unroll
        for (int j = 0; j < 4; j++)
            #pragma unroll
            for (int q = 0; q < 4; q++) acc[i][j][q] = 0.f;

    #pragma unroll
    for (int j = 0; j < 4; j++)
        aV[j] = mvalid ? *reinterpret_cast<const float4*>(arow + j * 4)
                       : make_float4(0.f, 0.f, 0.f, 0.f);
    bV[0] = *reinterpret_cast<const float4*>(brow);
    bV[1] = *reinterpret_cast<const float4*>(brow + 4);
    bV[2] = *reinterpret_cast<const float4*>(brow + NTOT);
    bV[3] = *reinterpret_cast<const float4*>(brow + NTOT + 4);

    for (int s = 0; s < NS; s++) {
        __syncthreads();

        #pragma unroll
        for (int j = 0; j < 4; j++)
            *reinterpret_cast<float4*>(&As[r][kh * 16 + j * 4]) = aV[j];

        {
            float r0[8], r1[8];
            *reinterpret_cast<float4*>(r0)     = bV[0];
            *reinterpret_cast<float4*>(r0 + 4) = bV[1];
            *reinterpret_cast<float4*>(r1)     = bV[2];
            *reinterpret_cast<float4*>(r1 + 4) = bV[3];
            #pragma unroll
            for (int j = 0; j < 8; j++) {
                int n  = c0 + j;
                int kx = BT_SWZ(n, 2 * bk2);
                *reinterpret_cast<float2*>(&Bt[n][kx]) = make_float2(r0[j], r1[j]);
            }
        }
        __syncthreads();

        if (s + 1 < NS) {
            const float* ap = arow + (s + 1) * 32;
            #pragma unroll
            for (int j = 0; j < 4; j++)
                aV[j] = mvalid ? *reinterpret_cast<const float4*>(ap + j * 4)
                               : make_float4(0.f, 0.f, 0.f, 0.f);
            const float* bp = brow + (size_t)(s + 1) * 32 * NTOT;
            bV[0] = *reinterpret_cast<const float4*>(bp);
            bV[1] = *reinterpret_cast<const float4*>(bp + 4);
            bV[2] = *reinterpret_cast<const float4*>(bp + NTOT);
            bV[3] = *reinterpret_cast<const float4*>(bp + NTOT + 4);
        }

        #pragma unroll
        for (int ks = 0; ks < 2; ks++) {
            const int kA = ks * 16 + tig * 2;
            uint32_t bh[4][2], bl[4][2];
            #pragma unroll
            for (int j = 0; j < 4; j++) {
                const int n   = wn * 32 + j * 8 + qid;
                const int kx0 = BT_SWZ(n, kA);
                const int kx1 = BT_SWZ(n, kA + 8);
                float2 p0 = *reinterpret_cast<const float2*>(&Bt[n][kx0]);
                float2 p1 = *reinterpret_cast<const float2*>(&Bt[n][kx1]);
                split2(p0, bh[j][0], bl[j][0]);
                split2(p1, bh[j][1], bl[j][1]);
            }
            #pragma unroll
            for (int i = 0; i < 4; i++) {
                const int R = wm * 64 + i * 16 + qid;
                float2 q0 = *reinterpret_cast<const float2*>(&As[R][kA]);
                float2 q1 = *reinterpret_cast<const float2*>(&As[R + 8][kA]);
                float2 q2 = *reinterpret_cast<const float2*>(&As[R][kA + 8]);
                float2 q3 = *reinterpret_cast<const float2*>(&As[R + 8][kA + 8]);
                uint32_t ah0, al0, ah1, al1, ah2, al2, ah3, al3;
                split2(q0, ah0, al0);
                split2(q1, ah1, al1);
                split2(q2, ah2, al2);
                split2(q3, ah3, al3);
                #pragma unroll
                for (int j = 0; j < 4; j++) {
                    mma_f16(acc[i][j], ah0, ah1, ah2, ah3, bh[j][0], bh[j][1]);
                    mma_f16(acc[i][j], al0, al1, al2, al3, bh[j][0], bh[j][1]);
                    mma_f16(acc[i][j], ah0, ah1, ah2, ah3, bl[j][0], bl[j][1]);
                }
            }
        }
    }

    const bool add_bias = RELU || (split == 0);
    #pragma unroll
    for (int i = 0; i < 4; i++) {
        const int mr0 = m0 + wm * 64 + i * 16 + qid;
        const int mr1 = mr0 + 8;
        const bool v0 = (mr0 < cnt), v1 = (mr1 < cnt);
        const int dr0 = v0 ? g_row[e][mr0] : 0;
        const int dr1 = v1 ? g_row[e][mr1] : 0;
        const float gt0 = RELU ? 1.f : (v0 ? g_gate[e][mr0] : 0.f);
        const float gt1 = RELU ? 1.f : (v1 ? g_gate[e][mr1] : 0.f);
        #pragma unroll
        for (int j = 0; j < 4; j++) {
            const int cl = wn * 32 + j * 8 + tig * 2;
            const float bz0 = add_bias ? bias_s[cl]     : 0.f;
            const float bz1 = add_bias ? bias_s[cl + 1] : 0.f;
            if (v0) {
                float y0 = acc[i][j][0] + bz0, y1 = acc[i][j][1] + bz1;
                float2 o;
                if (RELU) { o.x = fmaxf(y0, 0.f); o.y = fmaxf(y1, 0.f); }
                else      { o.x = gt0 * y0;       o.y = gt0 * y1; }
                *reinterpret_cast<float2*>(Dst + (size_t)dr0 * NTOT + n0 + cl) = o;
            }
            if (v1) {
                float y0 = acc[i][j][2] + bz0, y1 = acc[i][j][3] + bz1;
                float2 o;
                if (RELU) { o.x = fmaxf(y0, 0.f); o.y = fmaxf(y1, 0.f); }
                else      { o.x = gt1 * y0;       o.y = gt1 * y1; }
                *reinterpret_cast<float2*>(Dst + (size_t)dr1 * NTOT + n0 + cl) = o;
            }
        }
    }
}

// ===========================================================================
// out[t][d] = Y0[2t]+Y0[2t+1]+Y1[2t]+Y1[2t+1]
__global__ void combine_kernel(float* __restrict__ out) {
    int i = blockIdx.x * blockDim.x + threadIdx.x;
    if (i >= N_TOK * D_DIM / 4) return;
    int t  = i / (D_DIM / 4);
    int d4 = i % (D_DIM / 4);
    const float4* a0 = reinterpret_cast<const float4*>(g_Y  + (size_t)(2 * t)     * D_DIM) + d4;
    const float4* a1 = reinterpret_cast<const float4*>(g_Y  + (size_t)(2 * t + 1) * D_DIM) + d4;
    const float4* b0 = reinterpret_cast<const float4*>(g_Y2 + (size_t)(2 * t)     * D_DIM) + d4;
    const float4* b1 = reinterpret_cast<const float4*>(g_Y2 + (size_t)(2 * t + 1) * D_DIM) + d4;
    float4 p = *a0, q = *a1, r = *b0, s = *b1;
    reinterpret_cast<float4*>(out)[i] =
        make_float4(p.x + q.x + r.x + s.x, p.y + q.y + r.y + s.y,
                    p.z + q.z + r.z + s.z, p.w + q.w + r.w + s.w);
}

__global__ void aux_kernel(float* __restrict__ out, int out_size) {
    __shared__ float imp[E_NUM];
    int w = threadIdx.x >> 5, lane = threadIdx.x & 31;
    int cnt = g_cnt[w];
    float s = 0.f;
    for (int i = lane; i < cnt; i += 32) s += g_gate[w][i];
    #pragma unroll
    for (int off = 16; off > 0; off >>= 1) s += __shfl_down_sync(0xffffffffu, s, off);
    if (lane == 0) imp[w] = s;
    __syncthreads();
    if (threadIdx.x == 0) {
        float mean = 0.f;
        #pragma unroll
        for (int e = 0; e < E_NUM; e++) mean += imp[e];
        mean *= (1.f / E_NUM);
        float var = 0.f;
        #pragma unroll
        for (int e = 0; e < E_NUM; e++) { float d = imp[e] - mean; var += d * d; }
        var *= (1.f / (E_NUM - 1));
        float aux = 0.01f * var / (mean * mean + 1e-10f);
        if (out_size > N_TOK * D_DIM) out[out_size - 1] = aux;
    }
}

// ===========================================================================
extern "C" void kernel_launch(void* const* d_in, const int* in_sizes, int n_in,
                              void* d_out, int out_size) {
    const float* x  = (const float*)d_in[0];
    const float* wg = (const float*)d_in[1];
    const float* w1 = (const float*)d_in[2];
    const float* b1 = (const float*)d_in[3];
    const float* w2 = (const float*)d_in[4];
    const float* b2 = (const float*)d_in[5];
    float* out = (float*)d_out;

    reset_kernel<<<1, 32>>>();
    gating_kernel<<<N_TOK, 32>>>(x, wg);
    // GEMM1: g_H = relu(Xg @ W1 + b1); grid (16, 16, 16)
    moe_mma<D_DIM, D_DIM, H_DIM, true, 1>
        <<<dim3(H_DIM / 128, N_TOK / 128, E_NUM), 256>>>(x, w1, b1);
    // GEMM2 split-K=2: g_Y/g_Y2 = gate*(Hg @ W2 [+ b2 on split0]); grid (4, 16, 32)
    moe_mma<H_DIM, H_DIM, D_DIM, false, 2>
        <<<dim3(D_DIM / 128, N_TOK / 128, E_NUM * 2), 256>>>(x, w2, b2);
    combine_kernel<<<(N_TOK * D_DIM / 4 + 255) / 256, 256>>>(out);
    aux_kernel<<<1, 512>>>(out, out_size);
}

// round 11
// speedup vs baseline: 1.7388x; 1.2949x over previous
#include <cuda_runtime.h>
#include <cuda_fp16.h>
#include <cstdint>
#include <math.h>

// Problem constants
#define P_NUM 64
#define B_NUM 32
#define D_DIM 512
#define H_DIM 2048
#define E_NUM 16
#define N_TOK (P_NUM * B_NUM)        // 2048 tokens
#define N_ROWS (N_TOK * 2)           // 4096 assignment rows

// ---- device scratch. NEVER passed as kernel args from host (host-shadow/ATS
// trap confirmed R10). All kernels reference these symbols in device code. ----
__device__ int   g_cnt[E_NUM];
__device__ int   g_tok [E_NUM][N_TOK];
__device__ int   g_row [E_NUM][N_TOK];
__device__ float g_gate[E_NUM][N_TOK];

// pre-split f16 operands (u32 = packed pair of f16 along k)
__device__ __align__(16) uint32_t g_xs_hi[(size_t)N_TOK * (D_DIM / 2)];
__device__ __align__(16) uint32_t g_xs_lo[(size_t)N_TOK * (D_DIM / 2)];
__device__ __align__(16) uint32_t g_Hs_hi[(size_t)N_ROWS * (H_DIM / 2)];
__device__ __align__(16) uint32_t g_Hs_lo[(size_t)N_ROWS * (H_DIM / 2)];
// W transposed, slab-major: [E][K/32][N][16] u32
__device__ __align__(16) uint32_t g_w1t_hi[(size_t)E_NUM * (D_DIM / 32) * H_DIM * 16];
__device__ __align__(16) uint32_t g_w1t_lo[(size_t)E_NUM * (D_DIM / 32) * H_DIM * 16];
__device__ __align__(16) uint32_t g_w2t_hi[(size_t)E_NUM * (H_DIM / 32) * D_DIM * 16];
__device__ __align__(16) uint32_t g_w2t_lo[(size_t)E_NUM * (H_DIM / 32) * D_DIM * 16];

__device__ float g_Y [(size_t)N_ROWS * D_DIM]; // split-0 output
__device__ float g_Y2[(size_t)N_ROWS * D_DIM]; // split-1 output

// ===========================================================================
// helpers
// ===========================================================================
__device__ __forceinline__ void mma_f16(float* c,
                                        uint32_t a0, uint32_t a1, uint32_t a2, uint32_t a3,
                                        uint32_t b0, uint32_t b1) {
    asm volatile(
        "mma.sync.aligned.m16n8k16.row.col.f32.f16.f16.f32 "
        "{%0,%1,%2,%3}, {%4,%5,%6,%7}, {%8,%9}, {%0,%1,%2,%3};"
        : "+f"(c[0]), "+f"(c[1]), "+f"(c[2]), "+f"(c[3])
        : "r"(a0), "r"(a1), "r"(a2), "r"(a3), "r"(b0), "r"(b1));
}

__device__ __forceinline__ void ldm_x4(uint32_t& r0, uint32_t& r1,
                                       uint32_t& r2, uint32_t& r3, uint32_t addr) {
    asm volatile(
        "ldmatrix.sync.aligned.m8n8.x4.shared.b16 {%0,%1,%2,%3}, [%4];"
        : "=r"(r0), "=r"(r1), "=r"(r2), "=r"(r3) : "r"(addr));
}

__device__ __forceinline__ uint32_t smem_addr(const void* p) {
    return (uint32_t)__cvta_generic_to_shared(p);
}

__device__ __forceinline__ uint32_t pack2h(__half e0, __half e1) {
    return (uint32_t)__half_as_ushort(e0) |
           ((uint32_t)__half_as_ushort(e1) << 16);
}

__device__ __forceinline__ void split_pack(float v0, float v1,
                                           uint32_t& hi, uint32_t& lo) {
    __half h0 = __float2half_rn(v0);
    __half h1 = __float2half_rn(v1);
    __half l0 = __float2half_rn(v0 - __half2float(h0));
    __half l1 = __float2half_rn(v1 - __half2float(h1));
    hi = pack2h(h0, h1);
    lo = pack2h(l0, l1);
}

// ===========================================================================
// small kernels
// ===========================================================================
__global__ void reset_kernel() {
    if (threadIdx.x < E_NUM) g_cnt[threadIdx.x] = 0;
}

__global__ void gating_kernel(const float* __restrict__ x,
                              const float* __restrict__ wg) {
    int t = blockIdx.x;
    __shared__ float xs[D_DIM];
    __shared__ float vals[E_NUM];
    int tid = threadIdx.x; // 32

    const float4* xr = reinterpret_cast<const float4*>(x + (size_t)t * D_DIM);
    float4* xs4 = reinterpret_cast<float4*>(xs);
    #pragma unroll
    for (int i = tid; i < D_DIM / 4; i += 32) xs4[i] = xr[i];
    __syncwarp();

    if (tid < E_NUM) {
        float acc = 0.f;
        #pragma unroll 8
        for (int d = 0; d < D_DIM; d++) acc += xs[d] * wg[d * E_NUM + tid];
        vals[tid] = acc;
    }
    __syncwarp();

    if (tid == 0) {
        float v1 = -INFINITY, v2 = -INFINITY;
        int i1 = 0, i2 = 0;
        #pragma unroll
        for (int e = 0; e < E_NUM; e++) {
            float v = vals[e];
            if (v > v1) { v2 = v1; i2 = i1; v1 = v; i1 = e; }
            else if (v > v2) { v2 = v; i2 = e; }
        }
        float ex = __expf(v2 - v1);
        float inv = 1.f / (1.f + ex);
        int p1 = atomicAdd(&g_cnt[i1], 1);
        g_tok[i1][p1] = t; g_row[i1][p1] = 2 * t;     g_gate[i1][p1] = inv;
        int p2 = atomicAdd(&g_cnt[i2], 1);
        g_tok[i2][p2] = t; g_row[i2][p2] = 2 * t + 1; g_gate[i2][p2] = ex * inv;
    }
}

// ===========================================================================
// conversion kernels: fp32 -> f16 hi/lo packed pairs
// ===========================================================================
__global__ void convert_x(const float* __restrict__ x) {
    int t = blockIdx.x;
    int c = threadIdx.x;          // 0..255
    float2 v = *reinterpret_cast<const float2*>(x + (size_t)t * D_DIM + 2 * c);
    uint32_t hi, lo;
    split_pack(v.x, v.y, hi, lo);
    g_xs_hi[(size_t)t * (D_DIM / 2) + c] = hi;
    g_xs_lo[(size_t)t * (D_DIM / 2) + c] = lo;
}

// W [E][K][N] fp32 -> Wt [E][K/32][N][16] u32 (packed f16 pairs along k)
template<int K, int N, bool W1>
__global__ __launch_bounds__(256)
void convert_w(const float* __restrict__ w) {
    __shared__ float tile[32][65];
    const int e  = blockIdx.z;
    const int sl = blockIdx.y;
    const int nt = blockIdx.x;    // 64-wide n tile
    const int tid = threadIdx.x;

    const float* src = w + ((size_t)e * K + sl * 32) * N + nt * 64;
    const int kk = tid >> 3;            // 0..31
    const int nn = (tid & 7) * 8;       // 0..56
    float4 v0 = *reinterpret_cast<const float4*>(src + (size_t)kk * N + nn);
    float4 v1 = *reinterpret_cast<const float4*>(src + (size_t)kk * N + nn + 4);
    tile[kk][nn + 0] = v0.x; tile[kk][nn + 1] = v0.y;
    tile[kk][nn + 2] = v0.z; tile[kk][nn + 3] = v0.w;
    tile[kk][nn + 4] = v1.x; tile[kk][nn + 5] = v1.y;
    tile[kk][nn + 6] = v1.z; tile[kk][nn + 7] = v1.w;
    __syncthreads();

    uint32_t* oh = W1 ? g_w1t_hi : g_w2t_hi;
    uint32_t* ol = W1 ? g_w1t_lo : g_w2t_lo;
    const size_t obase = (((size_t)e * (K / 32) + sl) * N + (size_t)nt * 64) * 16;
    const int c = tid & 15;
    #pragma unroll
    for (int b = 0; b < 4; b++) {
        int n = (tid >> 4) + b * 16;   // 0..63
        uint32_t hi, lo;
        split_pack(tile[2 * c][n], tile[2 * c + 1][n], hi, lo);
        oh[obase + (size_t)n * 16 + c] = hi;
        ol[obase + (size_t)n * 16 + c] = lo;
    }
}

// ===========================================================================
// Grouped GEMM via mma.sync f16 (3x split), pre-split operands + ldmatrix.
// CTA tile 128x128, K-slab 32, 8 warps (wm 2 x wn 4), 4x4 mma tiles per warp.
// RELU=true : A = g_xs by g_tok; D = g_Hs (packed f16 hi/lo); relu(.+bias)
// RELU=false: A = g_Hs by g_row; D = g_Y/g_Y2 fp32; gate*(.+bias@split0)
// ===========================================================================
template<int KDIM, int NTOT, bool RELU, int NSPLIT>
__global__ __launch_bounds__(256)
void moe_mma(const float* __restrict__ bias) {
    const int e     = blockIdx.z / NSPLIT;
    const int split = blockIdx.z % NSPLIT;
    const int cnt = g_cnt[e];
    const int m0  = blockIdx.y * 128;
    if (m0 >= cnt) return;
    const int n0  = blockIdx.x * 128;

    const int KSEG  = KDIM / NSPLIT;
    const int kb    = split * KSEG;
    const int NSLAB = KDIM / 32;
    const int slab0 = kb / 32;
    const int NS    = KSEG / 32;

    __shared__ uint32_t sAh[128][20];
    __shared__ uint32_t sAl[128][20];
    __shared__ uint32_t sBh[128][20];
    __shared__ uint32_t sBl[128][20];
    __shared__ float bias_s[128];

    const int tid = threadIdx.x;
    const int wid = tid >> 5, lid = tid & 31;
    const int wm = wid & 1;
    const int wn = wid >> 1;
    const int qid = lid >> 2;
    const int tig = lid & 3;

    // device-symbol operand plumbing
    const uint32_t* Ahg = RELU ? g_xs_hi : g_Hs_hi;
    const uint32_t* Alg = RELU ? g_xs_lo : g_Hs_lo;
    const uint32_t* Whg = RELU ? g_w1t_hi : g_w2t_hi;
    const uint32_t* Wlg = RELU ? g_w1t_lo : g_w2t_lo;
    float* DstF = (split == 0) ? g_Y : g_Y2;

    if (tid < 128) bias_s[tid] = bias[(size_t)e * NTOT + n0 + tid];

    // ---- staging mapping: h = hi/lo select, rr = row within tile ----
    const int h  = tid >> 7;       // 0 = hi, 1 = lo
    const int rr = tid & 127;
    const int mrow = m0 + rr;
    const bool mvalid = (mrow < cnt);
    const int aidx = mvalid ? (RELU ? g_tok[e][mrow] : g_row[e][mrow]) : 0;
    const uint32_t* agp = (h ? Alg : Ahg) + (size_t)aidx * (KDIM / 2) + (kb >> 1);
    const uint32_t* wgp = (h ? Wlg : Whg)
        + ((size_t)e * NSLAB + slab0) * NTOT * 16 + (size_t)(n0 + rr) * 16;

    // ---- ldmatrix base addresses (byte, shared space); smem row = 80 B ----
    const uint32_t aAh = smem_addr(&sAh[wm * 64 + (lid & 15)][(lid >> 4) * 4]);
    const uint32_t aAl = smem_addr(&sAl[wm * 64 + (lid & 15)][(lid >> 4) * 4]);
    const int brow = wn * 32 + (lid >> 4) * 8 + (lid & 7);
    const int bcol = ((lid >> 3) & 1) * 4;
    const uint32_t aBh = smem_addr(&sBh[brow][bcol]);
    const uint32_t aBl = smem_addr(&sBl[brow][bcol]);

    float acc[4][4][4];
    #pragma unroll
    for (int i = 0; i < 4; i++)
        #pragma unroll
        for (int j = 0; j < 4; j++)
            #pragma unroll
            for (int q = 0; q < 4; q++) acc[i][j][q] = 0.f;

    uint4 pA[4], pB[4];
    const uint4 z4 = make_uint4(0u, 0u, 0u, 0u);
    #pragma unroll
    for (int j = 0; j < 4; j++) {
        pA[j] = mvalid ? *reinterpret_cast<const uint4*>(agp + j * 4) : z4;
        pB[j] = *reinterpret_cast<const uint4*>(wgp + j * 4);
    }

    for (int s = 0; s < NS; s++) {
        __syncthreads();   // previous compute done reading smem

        {
            uint32_t (*sA)[20] = h ? sAl : sAh;
            uint32_t (*sB)[20] = h ? sBl : sBh;
            #pragma unroll
            for (int j = 0; j < 4; j++) {
                *reinterpret_cast<uint4*>(&sA[rr][j * 4]) = pA[j];
                *reinterpret_cast<uint4*>(&sB[rr][j * 4]) = pB[j];
            }
        }
        __syncthreads();

        if (s + 1 < NS) {
            const uint32_t* ap = agp + (size_t)(s + 1) * 16;
            const uint32_t* bp = wgp + (size_t)(s + 1) * NTOT * 16;
            #pragma unroll
            for (int j = 0; j < 4; j++) {
                pA[j] = mvalid ? *reinterpret_cast<const uint4*>(ap + j * 4) : z4;
                pB[j] = *reinterpret_cast<const uint4*>(bp + j * 4);
            }
        }

        #pragma unroll
        for (int ks = 0; ks < 2; ks++) {
            const uint32_t cb = ks * 32;   // 8 u32 = 32 bytes column shift
            uint32_t bh[4][2], bl[4][2];
            #pragma unroll
            for (int jj = 0; jj < 2; jj++) {
                ldm_x4(bh[jj * 2][0], bh[jj * 2][1],
                       bh[jj * 2 + 1][0], bh[jj * 2 + 1][1],
                       aBh + jj * (16 * 80) + cb);
                ldm_x4(bl[jj * 2][0], bl[jj * 2][1],
                       bl[jj * 2 + 1][0], bl[jj * 2 + 1][1],
                       aBl + jj * (16 * 80) + cb);
            }
            #pragma unroll
            for (int i = 0; i < 4; i++) {
                uint32_t ah0, ah1, ah2, ah3, al0, al1, al2, al3;
                ldm_x4(ah0, ah1, ah2, ah3, aAh + i * (16 * 80) + cb);
                ldm_x4(al0, al1, al2, al3, aAl + i * (16 * 80) + cb);
                #pragma unroll
                for (int j = 0; j < 4; j++) {
                    mma_f16(acc[i][j], ah0, ah1, ah2, ah3, bh[j][0], bh[j][1]);
                    mma_f16(acc[i][j], al0, al1, al2, al3, bh[j][0], bh[j][1]);
                    mma_f16(acc[i][j], ah0, ah1, ah2, ah3, bl[j][0], bl[j][1]);
                }
            }
        }
    }

    // ---- epilogue ----
    const bool add_bias = RELU || (split == 0);
    #pragma unroll
    for (int i = 0; i < 4; i++) {
        const int mr0 = m0 + wm * 64 + i * 16 + qid;
        const int mr1 = mr0 + 8;
        const bool v0 = (mr0 < cnt), v1 = (mr1 < cnt);
        const int dr0 = v0 ? g_row[e][mr0] : 0;
        const int dr1 = v1 ? g_row[e][mr1] : 0;
        const float gt0 = RELU ? 1.f : (v0 ? g_gate[e][mr0] : 0.f);
        const float gt1 = RELU ? 1.f : (v1 ? g_gate[e][mr1] : 0.f);
        #pragma unroll
        for (int j = 0; j < 4; j++) {
            const int cl = wn * 32 + j * 8 + tig * 2;
            const float bz0 = add_bias ? bias_s[cl]     : 0.f;
            const float bz1 = add_bias ? bias_s[cl + 1] : 0.f;
            if (RELU) {
                const size_t hcol = (size_t)((n0 + cl) >> 1);
                if (v0) {
                    float y0 = fmaxf(acc[i][j][0] + bz0, 0.f);
                    float y1 = fmaxf(acc[i][j][1] + bz1, 0.f);
                    uint32_t hi, lo;
                    split_pack(y0, y1, hi, lo);
                    g_Hs_hi[(size_t)dr0 * (NTOT / 2) + hcol] = hi;
                    g_Hs_lo[(size_t)dr0 * (NTOT / 2) + hcol] = lo;
                }
                if (v1) {
                    float y0 = fmaxf(acc[i][j][2] + bz0, 0.f);
                    float y1 = fmaxf(acc[i][j][3] + bz1, 0.f);
                    uint32_t hi, lo;
                    split_pack(y0, y1, hi, lo);
                    g_Hs_hi[(size_t)dr1 * (NTOT / 2) + hcol] = hi;
                    g_Hs_lo[(size_t)dr1 * (NTOT / 2) + hcol] = lo;
                }
            } else {
                if (v0) {
                    float2 o;
                    o.x = gt0 * (acc[i][j][0] + bz0);
                    o.y = gt0 * (acc[i][j][1] + bz1);
                    *reinterpret_cast<float2*>(DstF + (size_t)dr0 * NTOT + n0 + cl) = o;
                }
                if (v1) {
                    float2 o;
                    o.x = gt1 * (acc[i][j][2] + bz0);
                    o.y = gt1 * (acc[i][j][3] + bz1);
                    *reinterpret_cast<float2*>(DstF + (size_t)dr1 * NTOT + n0 + cl) = o;
                }
            }
        }
    }
}

// ===========================================================================
// out[t][d] = Y0[2t]+Y0[2t+1]+Y1[2t]+Y1[2t+1]
__global__ void combine_kernel(float* __restrict__ out) {
    int i = blockIdx.x * blockDim.x + threadIdx.x;
    if (i >= N_TOK * D_DIM / 4) return;
    int t  = i / (D_DIM / 4);
    int d4 = i % (D_DIM / 4);
    const float4* a0 = reinterpret_cast<const float4*>(g_Y  + (size_t)(2 * t)     * D_DIM) + d4;
    const float4* a1 = reinterpret_cast<const float4*>(g_Y  + (size_t)(2 * t + 1) * D_DIM) + d4;
    const float4* b0 = reinterpret_cast<const float4*>(g_Y2 + (size_t)(2 * t)     * D_DIM) + d4;
    const float4* b1 = reinterpret_cast<const float4*>(g_Y2 + (size_t)(2 * t + 1) * D_DIM) + d4;
    float4 p = *a0, q = *a1, r = *b0, s = *b1;
    reinterpret_cast<float4*>(out)[i] =
        make_float4(p.x + q.x + r.x + s.x, p.y + q.y + r.y + s.y,
                    p.z + q.z + r.z + s.z, p.w + q.w + r.w + s.w);
}

__global__ void aux_kernel(float* __restrict__ out, int out_size) {
    __shared__ float imp[E_NUM];
    int w = threadIdx.x >> 5, lane = threadIdx.x & 31;
    int cnt = g_cnt[w];
    float s = 0.f;
    for (int i = lane; i < cnt; i += 32) s += g_gate[w][i];
    #pragma unroll
    for (int off = 16; off > 0; off >>= 1) s += __shfl_down_sync(0xffffffffu, s, off);
    if (lane == 0) imp[w] = s;
    __syncthreads();
    if (threadIdx.x == 0) {
        float mean = 0.f;
        #pragma unroll
        for (int e = 0; e < E_NUM; e++) mean += imp[e];
        mean *= (1.f / E_NUM);
        float var = 0.f;
        #pragma unroll
        for (int e = 0; e < E_NUM; e++) { float d = imp[e] - mean; var += d * d; }
        var *= (1.f / (E_NUM - 1));
        float aux = 0.01f * var / (mean * mean + 1e-10f);
        if (out_size > N_TOK * D_DIM) out[out_size - 1] = aux;
    }
}

// ===========================================================================
extern "C" void kernel_launch(void* const* d_in, const int* in_sizes, int n_in,
                              void* d_out, int out_size) {
    const float* x  = (const float*)d_in[0];
    const float* wg = (const float*)d_in[1];
    const float* w1 = (const float*)d_in[2];
    const float* b1 = (const float*)d_in[3];
    const float* w2 = (const float*)d_in[4];
    const float* b2 = (const float*)d_in[5];
    float* out = (float*)d_out;

    reset_kernel<<<1, 32>>>();
    gating_kernel<<<N_TOK, 32>>>(x, wg);
    // pre-split operands to f16 hi/lo
    convert_x<<<N_TOK, 256>>>(x);
    convert_w<D_DIM, H_DIM, true ><<<dim3(H_DIM / 64, D_DIM / 32, E_NUM), 256>>>(w1);
    convert_w<H_DIM, D_DIM, false><<<dim3(D_DIM / 64, H_DIM / 32, E_NUM), 256>>>(w2);
    // GEMM1: g_Hs = relu(Xg @ W1 + b1); grid (16, 16, 16)
    moe_mma<D_DIM, H_DIM, true, 1>
        <<<dim3(H_DIM / 128, N_TOK / 128, E_NUM), 256>>>(b1);
    // GEMM2 split-K=2: g_Y/g_Y2 = gate*(Hg @ W2 [+ b2 on split0]); grid (4, 16, 32)
    moe_mma<H_DIM, D_DIM, false, 2>
        <<<dim3(D_DIM / 128, N_TOK / 128, E_NUM * 2), 256>>>(b2);
    combine_kernel<<<(N_TOK * D_DIM / 4 + 255) / 256, 256>>>(out);
    aux_kernel<<<1, 512>>>(out, out_size);
}